// round 17
// baseline (speedup 1.0000x reference)
#include <cuda_runtime.h>
#include <cuda_fp16.h>
#include <math.h>

#define TSEQ 2048
#define NB   2
#define CDIM 768
#define NH   12
#define HDIM 64
#define DFF  3072
#define ROWS (NB * TSEQ)   // 4096

// ---------------- scratch (device globals: allocation-free) ----------------
__device__ __half g_lnh [ROWS * CDIM];
__device__ __half g_qkvh[ROWS * 3 * CDIM];
__device__ __half g_atth[ROWS * CDIM];
__device__ float  g_x1  [ROWS * CDIM];
__device__ __half g_hh  [ROWS * DFF];
__device__ __half g_wqkv_h [CDIM * 3 * CDIM];
__device__ __half g_wo_h   [CDIM * CDIM];
__device__ __half g_wfc_h  [CDIM * DFF];
__device__ __half g_wproj_h[DFF * CDIM];

__device__ __forceinline__ float gelu_f(float v) {
    return 0.5f * v * (1.0f + erff(v * 0.70710678118654752f));
}

union Pack4 { __half h[4]; uint2 u; };

__device__ __forceinline__ void cp16(unsigned dst, const void* src) {
    asm volatile("cp.async.cg.shared.global [%0], [%1], 16;\n"
                 :: "r"(dst), "l"(src) : "memory");
}
__device__ __forceinline__ void cp_commit() {
    asm volatile("cp.async.commit_group;\n" ::: "memory");
}
__device__ __forceinline__ void ldsm4(unsigned* r, unsigned addr) {
    asm volatile("ldmatrix.sync.aligned.m8n8.x4.shared.b16 {%0,%1,%2,%3}, [%4];"
                 : "=r"(r[0]), "=r"(r[1]), "=r"(r[2]), "=r"(r[3]) : "r"(addr));
}
__device__ __forceinline__ void ldsm4t(unsigned* r, unsigned addr) {
    asm volatile("ldmatrix.sync.aligned.m8n8.x4.trans.shared.b16 {%0,%1,%2,%3}, [%4];"
                 : "=r"(r[0]), "=r"(r[1]), "=r"(r[2]), "=r"(r[3]) : "r"(addr));
}
__device__ __forceinline__ void ldsm2t(unsigned& r0, unsigned& r1, unsigned addr) {
    asm volatile("ldmatrix.sync.aligned.m8n8.x2.trans.shared.b16 {%0,%1}, [%2];"
                 : "=r"(r0), "=r"(r1) : "r"(addr));
}
__device__ __forceinline__ void mma16816(float* c, const unsigned* a,
                                         unsigned b0, unsigned b1) {
    asm volatile(
        "mma.sync.aligned.m16n8k16.row.col.f32.f16.f16.f32 "
        "{%0,%1,%2,%3}, {%4,%5,%6,%7}, {%8,%9}, {%0,%1,%2,%3};"
        : "+f"(c[0]), "+f"(c[1]), "+f"(c[2]), "+f"(c[3])
        : "r"(a[0]), "r"(a[1]), "r"(a[2]), "r"(a[3]), "r"(b0), "r"(b1));
}
__device__ __forceinline__ unsigned f22h2(float x, float y) {
    __half2 h = __floats2half2_rn(x, y);
    return *(unsigned*)&h;
}
__device__ __forceinline__ unsigned h2exp2_u(unsigned x) {
    unsigned r;
    asm("ex2.approx.f16x2 %0, %1;" : "=r"(r) : "r"(x));
    return r;
}

// ---------------- weight conversions (split for stream overlap) ------------
#define N4_QKV  (CDIM * 3 * CDIM / 4)
#define N4_O    (CDIM * CDIM / 4)
#define N4_FC   (CDIM * DFF / 4)
#define N4_PROJ (DFF * CDIM / 4)
#define N4_R3   (N4_O + N4_FC + N4_PROJ)

__device__ __forceinline__ void cvt4(const float4* src, uint2* dst, int off) {
    float4 v0 = src[off + 0], v1 = src[off + 1],
           v2 = src[off + 2], v3 = src[off + 3];
    Pack4 p0, p1, p2, p3;
    p0.h[0] = __float2half_rn(v0.x); p0.h[1] = __float2half_rn(v0.y);
    p0.h[2] = __float2half_rn(v0.z); p0.h[3] = __float2half_rn(v0.w);
    p1.h[0] = __float2half_rn(v1.x); p1.h[1] = __float2half_rn(v1.y);
    p1.h[2] = __float2half_rn(v1.z); p1.h[3] = __float2half_rn(v1.w);
    p2.h[0] = __float2half_rn(v2.x); p2.h[1] = __float2half_rn(v2.y);
    p2.h[2] = __float2half_rn(v2.z); p2.h[3] = __float2half_rn(v2.w);
    p3.h[0] = __float2half_rn(v3.x); p3.h[1] = __float2half_rn(v3.y);
    p3.h[2] = __float2half_rn(v3.z); p3.h[3] = __float2half_rn(v3.w);
    dst[off + 0] = p0.u; dst[off + 1] = p1.u;
    dst[off + 2] = p2.u; dst[off + 3] = p3.u;
}

__global__ __launch_bounds__(256) void round1_k(const float* __restrict__ wqkv,
                                                __half* __restrict__ oqkv) {
    int base = (blockIdx.x * 256 + threadIdx.x) * 4;
    if (base >= N4_QKV) return;
    cvt4((const float4*)wqkv, (uint2*)oqkv, base);
}

__global__ __launch_bounds__(256) void round3_k(const float* __restrict__ wo,
                                                const float* __restrict__ wfc,
                                                const float* __restrict__ wproj,
                                                __half* __restrict__ oo,
                                                __half* __restrict__ ofc,
                                                __half* __restrict__ oproj) {
    int base = (blockIdx.x * 256 + threadIdx.x) * 4;
    if (base >= N4_R3) return;
    if (base < N4_O) {
        cvt4((const float4*)wo, (uint2*)oo, base);
    } else if (base < N4_O + N4_FC) {
        cvt4((const float4*)wfc, (uint2*)ofc, base - N4_O);
    } else {
        cvt4((const float4*)wproj, (uint2*)oproj, base - N4_O - N4_FC);
    }
}

// ---------------- LayerNorm: one warp per row (fp32 in, fp16 out) ----------
__global__ __launch_bounds__(256) void ln_k(const float* __restrict__ xin,
                                            const float* __restrict__ g,
                                            const float* __restrict__ b,
                                            __half* __restrict__ out) {
    int row  = blockIdx.x * 8 + (threadIdx.x >> 5);
    int lane = threadIdx.x & 31;
    const float4* xr = (const float4*)(xin + (size_t)row * CDIM);

    float4 v[6];
    float s = 0.f, ss = 0.f;
    #pragma unroll
    for (int i = 0; i < 6; ++i) {
        v[i] = xr[i * 32 + lane];
        s  += v[i].x + v[i].y + v[i].z + v[i].w;
        ss += v[i].x * v[i].x + v[i].y * v[i].y
            + v[i].z * v[i].z + v[i].w * v[i].w;
    }
    #pragma unroll
    for (int off = 16; off > 0; off >>= 1) {
        s  += __shfl_xor_sync(0xffffffffu, s,  off);
        ss += __shfl_xor_sync(0xffffffffu, ss, off);
    }

    const float inv = 1.0f / (float)CDIM;
    float mu   = s * inv;
    float var  = ss * inv - mu * mu;
    float rstd = rsqrtf(var + 1e-5f);

    const float4* g4 = (const float4*)g;
    const float4* b4 = (const float4*)b;
    __half* orow = out + (size_t)row * CDIM;
    #pragma unroll
    for (int i = 0; i < 6; ++i) {
        int c4 = i * 32 + lane;
        float4 gv = g4[c4];
        float4 bv = b4[c4];
        Pack4 p;
        p.h[0] = __float2half_rn((v[i].x - mu) * rstd * gv.x + bv.x);
        p.h[1] = __float2half_rn((v[i].y - mu) * rstd * gv.y + bv.y);
        p.h[2] = __float2half_rn((v[i].z - mu) * rstd * gv.z + bv.z);
        p.h[3] = __float2half_rn((v[i].w - mu) * rstd * gv.w + bv.w);
        *(uint2*)(orow + c4 * 4) = p.u;
    }
}

// ---------------- fp16 GEMM (BM=128): single-sync 3-stage pipeline ---------
// EPI: 1 +res(f32), 2 +bias+GELU(fp16), 3 +bias+res(f32), 4 none(fp16)
#define BN 128
#define BK 32
#define AROW2 40
#define BROW2 136
#define BSZ2 (BK * BROW2 * 2)
#define NSTG 3

#define ASZ128 (128 * AROW2 * 2)
#define STG128 (ASZ128 + BSZ2)
#define GEMM_SMEM128 (NSTG * STG128)

template <int EPI>
__global__ __launch_bounds__(128, 2) void gemm_k(const __half* __restrict__ A,
                                                 const __half* __restrict__ Bm,
                                                 const float* __restrict__ bias,
                                                 const float* __restrict__ res,
                                                 void* __restrict__ Cv,
                                                 int M, int N, int K) {
    extern __shared__ char smc[];
    unsigned smem_base = (unsigned)__cvta_generic_to_shared(smc);

    int tid  = threadIdx.x;
    int lane = tid & 31;
    int wid  = tid >> 5;
    int warp_m = wid & 1;
    int warp_n = wid >> 1;
    int bm = blockIdx.y * 128;
    int bn = blockIdx.x * BN;
    int grp = lane >> 2;
    int tig = lane & 3;

    const __half* aP[4]; unsigned aO[4];
    const __half* bP[4]; unsigned bO[4];
    #pragma unroll
    for (int l = 0; l < 4; ++l) {
        int idx = l * 128 + tid;
        int ar = idx >> 2, ac = idx & 3;
        aP[l] = A + (size_t)(bm + ar) * K + ac * 8;
        aO[l] = (unsigned)(ar * AROW2 + ac * 8) * 2u;
        int br = idx >> 4, bc = idx & 15;
        bP[l] = Bm + (size_t)br * N + bn + bc * 8;
        bO[l] = (unsigned)ASZ128 + (unsigned)(br * BROW2 + bc * 8) * 2u;
    }

    auto stage = [&](int t) {
        unsigned s = smem_base + (unsigned)(t % NSTG) * STG128;
        #pragma unroll
        for (int l = 0; l < 4; ++l) {
            cp16(s + aO[l], aP[l] + (size_t)t * BK);
            cp16(s + bO[l], bP[l] + (size_t)t * BK * N);
        }
        cp_commit();
    };

    float acc[4][8][4];
    #pragma unroll
    for (int i = 0; i < 4; ++i)
        #pragma unroll
        for (int j = 0; j < 8; ++j)
            #pragma unroll
            for (int r = 0; r < 4; ++r) acc[i][j][r] = 0.f;

    int ntiles = K / BK;
    stage(0); stage(1);

    unsigned aLrow = (unsigned)(warp_m * 64 + (lane & 15));
    unsigned aLcol = (unsigned)((lane >> 4) * 8);
    unsigned bLrow = (unsigned)(lane & 15);
    unsigned bLcol = (unsigned)(warp_n * 64 + (lane >> 4) * 8);

    for (int t = 0; t < ntiles; ++t) {
        if (t + 1 < ntiles) {
            asm volatile("cp.async.wait_group %0;\n" :: "n"(1));
        } else {
            asm volatile("cp.async.wait_group %0;\n" :: "n"(0));
        }
        __syncthreads();
        if (t + 2 < ntiles) stage(t + 2);

        unsigned base = smem_base + (unsigned)(t % NSTG) * STG128;

        #pragma unroll
        for (int ks = 0; ks < 2; ++ks) {
            unsigned af[4][4], bf[4][4];
            #pragma unroll
            for (int mi = 0; mi < 4; ++mi)
                ldsm4(af[mi], base +
                      (unsigned)(((aLrow + mi * 16) * AROW2) + ks * 16 + aLcol) * 2);
            #pragma unroll
            for (int j = 0; j < 4; ++j)
                ldsm4t(bf[j], base + (unsigned)ASZ128 +
                       (unsigned)(((ks * 16 + bLrow) * BROW2) + bLcol + j * 16) * 2);

            #pragma unroll
            for (int mi = 0; mi < 4; ++mi)
                #pragma unroll
                for (int ni = 0; ni < 8; ++ni)
                    mma16816(acc[mi][ni], af[mi],
                             bf[ni >> 1][(ni & 1) * 2 + 0],
                             bf[ni >> 1][(ni & 1) * 2 + 1]);
        }
    }

    #pragma unroll
    for (int mi = 0; mi < 4; ++mi) {
        #pragma unroll
        for (int rr = 0; rr < 2; ++rr) {
            int r = bm + warp_m * 64 + mi * 16 + grp + rr * 8;
            #pragma unroll
            for (int ni = 0; ni < 8; ++ni) {
                int c = bn + warp_n * 64 + ni * 8 + 2 * tig;
                float v0 = acc[mi][ni][rr * 2 + 0];
                float v1 = acc[mi][ni][rr * 2 + 1];
                if (EPI == 2 || EPI == 3) { v0 += bias[c]; v1 += bias[c + 1]; }
                if (EPI == 2)             { v0 = gelu_f(v0); v1 = gelu_f(v1); }
                if (EPI == 1 || EPI == 3) {
                    const float* rp = res + (size_t)r * N + c;
                    v0 += rp[0]; v1 += rp[1];
                }
                if (EPI == 2 || EPI == 4) {
                    __half2 o;
                    o.x = __float2half_rn(v0);
                    o.y = __float2half_rn(v1);
                    *(__half2*)((__half*)Cv + (size_t)r * N + c) = o;
                } else {
                    float2 o2; o2.x = v0; o2.y = v1;
                    *(float2*)((float*)Cv + (size_t)r * N + c) = o2;
                }
            }
        }
    }
}

// ---------------- fp16 GEMM (BM=64): single-sync 3-stage -------------------
#define ASZ64 (64 * AROW2 * 2)
#define STG64 (ASZ64 + BSZ2)
#define GEMM_SMEM64 (NSTG * STG64)

template <int EPI>
__global__ __launch_bounds__(128, 4) void gemm64_k(const __half* __restrict__ A,
                                                   const __half* __restrict__ Bm,
                                                   const float* __restrict__ bias,
                                                   const float* __restrict__ res,
                                                   void* __restrict__ Cv,
                                                   int M, int N, int K) {
    extern __shared__ char smc[];
    unsigned smem_base = (unsigned)__cvta_generic_to_shared(smc);

    int tid  = threadIdx.x;
    int lane = tid & 31;
    int wid  = tid >> 5;
    int warp_m = wid & 1;
    int warp_n = wid >> 1;
    int bm = blockIdx.y * 64;
    int bn = blockIdx.x * BN;
    int grp = lane >> 2;
    int tig = lane & 3;

    const __half* aP[2]; unsigned aO[2];
    const __half* bP[4]; unsigned bO[4];
    #pragma unroll
    for (int l = 0; l < 2; ++l) {
        int idx = l * 128 + tid;
        int ar = idx >> 2, ac = idx & 3;
        aP[l] = A + (size_t)(bm + ar) * K + ac * 8;
        aO[l] = (unsigned)(ar * AROW2 + ac * 8) * 2u;
    }
    #pragma unroll
    for (int l = 0; l < 4; ++l) {
        int idx = l * 128 + tid;
        int br = idx >> 4, bc = idx & 15;
        bP[l] = Bm + (size_t)br * N + bn + bc * 8;
        bO[l] = (unsigned)ASZ64 + (unsigned)(br * BROW2 + bc * 8) * 2u;
    }

    auto stage = [&](int t) {
        unsigned s = smem_base + (unsigned)(t % NSTG) * STG64;
        #pragma unroll
        for (int l = 0; l < 2; ++l)
            cp16(s + aO[l], aP[l] + (size_t)t * BK);
        #pragma unroll
        for (int l = 0; l < 4; ++l)
            cp16(s + bO[l], bP[l] + (size_t)t * BK * N);
        cp_commit();
    };

    float acc[2][8][4];
    #pragma unroll
    for (int i = 0; i < 2; ++i)
        #pragma unroll
        for (int j = 0; j < 8; ++j)
            #pragma unroll
            for (int r = 0; r < 4; ++r) acc[i][j][r] = 0.f;

    int ntiles = K / BK;
    stage(0); stage(1);

    unsigned aLrow = (unsigned)(warp_m * 32 + (lane & 15));
    unsigned aLcol = (unsigned)((lane >> 4) * 8);
    unsigned bLrow = (unsigned)(lane & 15);
    unsigned bLcol = (unsigned)(warp_n * 64 + (lane >> 4) * 8);

    for (int t = 0; t < ntiles; ++t) {
        if (t + 1 < ntiles) {
            asm volatile("cp.async.wait_group %0;\n" :: "n"(1));
        } else {
            asm volatile("cp.async.wait_group %0;\n" :: "n"(0));
        }
        __syncthreads();
        if (t + 2 < ntiles) stage(t + 2);

        unsigned base = smem_base + (unsigned)(t % NSTG) * STG64;

        #pragma unroll
        for (int ks = 0; ks < 2; ++ks) {
            unsigned af[2][4], bf[4][4];
            #pragma unroll
            for (int mi = 0; mi < 2; ++mi)
                ldsm4(af[mi], base +
                      (unsigned)(((aLrow + mi * 16) * AROW2) + ks * 16 + aLcol) * 2);
            #pragma unroll
            for (int j = 0; j < 4; ++j)
                ldsm4t(bf[j], base + (unsigned)ASZ64 +
                       (unsigned)(((ks * 16 + bLrow) * BROW2) + bLcol + j * 16) * 2);

            #pragma unroll
            for (int mi = 0; mi < 2; ++mi)
                #pragma unroll
                for (int ni = 0; ni < 8; ++ni)
                    mma16816(acc[mi][ni], af[mi],
                             bf[ni >> 1][(ni & 1) * 2 + 0],
                             bf[ni >> 1][(ni & 1) * 2 + 1]);
        }
    }

    #pragma unroll
    for (int mi = 0; mi < 2; ++mi) {
        #pragma unroll
        for (int rr = 0; rr < 2; ++rr) {
            int r = bm + warp_m * 32 + mi * 16 + grp + rr * 8;
            #pragma unroll
            for (int ni = 0; ni < 8; ++ni) {
                int c = bn + warp_n * 64 + ni * 8 + 2 * tig;
                float v0 = acc[mi][ni][rr * 2 + 0];
                float v1 = acc[mi][ni][rr * 2 + 1];
                if (EPI == 2 || EPI == 3) { v0 += bias[c]; v1 += bias[c + 1]; }
                if (EPI == 2)             { v0 = gelu_f(v0); v1 = gelu_f(v1); }
                if (EPI == 1 || EPI == 3) {
                    const float* rp = res + (size_t)r * N + c;
                    v0 += rp[0]; v1 += rp[1];
                }
                if (EPI == 2 || EPI == 4) {
                    __half2 o;
                    o.x = __float2half_rn(v0);
                    o.y = __float2half_rn(v1);
                    *(__half2*)((__half*)Cv + (size_t)r * N + c) = o;
                } else {
                    float2 o2; o2.x = v0; o2.y = v1;
                    *(float2*)((float*)Cv + (size_t)r * N + c) = o2;
                }
            }
        }
    }
}

// ---------------- Flash attention: 3-stage KV, single sync, dead-tile skip -
#define KVP 72
#define Q_HALVES   (128 * KVP)
#define KV_STAGE_H (2 * 64 * KVP)
#define KVSTG 3
#define ATT_SMEM   ((Q_HALVES + KVSTG * KV_STAGE_H) * 2)   // 73728 B
#define QSCALE     0.1803368801111244f   // 0.125 * log2(e)

__global__ __launch_bounds__(256, 2) void attn_k(const __half* __restrict__ qkvh,
                                                 __half* __restrict__ y) {
    extern __shared__ __half smh[];
    unsigned smem_b = (unsigned)__cvta_generic_to_shared(smh);
    unsigned kvb    = smem_b + Q_HALVES * 2;

    int bh = blockIdx.y;
    int b  = bh / NH;
    int h  = bh % NH;
    int qt = gridDim.x - 1 - blockIdx.x;
    int q0 = qt * 128;
    size_t bT = (size_t)b * TSEQ;

    int tid  = threadIdx.x;
    int lane = tid & 31;
    int wid  = tid >> 5;
    int grp  = lane >> 2;
    int tig  = lane & 3;

    if (tid < 192) {
        int sbuf = tid >> 6, r = tid & 63;
        __half* vp = smh + Q_HALVES + sbuf * KV_STAGE_H + 64 * KVP + r * KVP + 64;
        uint4 ones = {0x00003C00u, 0u, 0u, 0u};
        *(uint4*)vp = ones;
    }

    #pragma unroll
    for (int i = 0; i < 4; ++i) {
        int c = i * 256 + tid;
        int row = c >> 3, col8 = c & 7;
        const __half* src = qkvh + (bT + q0 + row) * (3 * CDIM) + h * HDIM + col8 * 8;
        cp16(smem_b + (unsigned)(row * KVP + col8 * 8) * 2, src);
    }
    cp_commit();

    auto kvissue = [&](int t) {
        int k0 = t * 64;
        unsigned sb = kvb + (unsigned)(t % KVSTG) * (KV_STAGE_H * 2);
        #pragma unroll
        for (int i = 0; i < 4; ++i) {
            int c = i * 256 + tid;
            int isV = c >> 9;
            int cc = c & 511;
            int row = cc >> 3, col8 = cc & 7;
            const __half* src = qkvh + (bT + k0 + row) * (3 * CDIM)
                                + (1 + isV) * CDIM + h * HDIM + col8 * 8;
            cp16(sb + (unsigned)(isV * (64 * KVP) + row * KVP + col8 * 8) * 2, src);
        }
        cp_commit();
    };

    int ntiles = 2 * (qt + 1);
    kvissue(0);
    asm volatile("cp.async.wait_group 0;\n" ::: "memory");
    __syncthreads();

    unsigned qf[4][4];
    {
        unsigned rowb = smem_b + (unsigned)((wid * 16 + (lane & 15)) * KVP) * 2;
        #pragma unroll
        for (int ch = 0; ch < 4; ++ch) {
            ldsm4(qf[ch], rowb + (unsigned)(ch * 16 + (lane >> 4) * 8) * 2);
            __half2 sc = __floats2half2_rn(QSCALE, QSCALE);
            #pragma unroll
            for (int r = 0; r < 4; ++r) {
                __half2 v = *(__half2*)&qf[ch][r];
                v = __hmul2(v, sc);
                qf[ch][r] = *(unsigned*)&v;
            }
        }
    }
    // constant ones-fragment for the l-MMA
    unsigned w0c, w1c;
    ldsm2t(w0c, w1c, kvb + (unsigned)(64 * KVP) * 2
                        + (unsigned)(((lane & 15)) * KVP + 64) * 2);

    if (1 < ntiles) kvissue(1);

    float o[8][4];
    #pragma unroll
    for (int i = 0; i < 8; ++i)
        #pragma unroll
        for (int j = 0; j < 4; ++j) o[i][j] = 0.f;
    float lacc[4];
    lacc[0] = lacc[1] = lacc[2] = lacc[3] = 0.f;
    float m0 = -1e30f, m1 = -1e30f;

    int r0g = q0 + wid * 16 + grp;
    int wmaxrow = q0 + wid * 16 + 15;

    for (int t = 0; t < ntiles; ++t) {
        if (t + 1 < ntiles) {
            asm volatile("cp.async.wait_group 1;\n" ::: "memory");
        } else {
            asm volatile("cp.async.wait_group 0;\n" ::: "memory");
        }
        __syncthreads();
        if (t + 2 < ntiles) kvissue(t + 2);

        int k0 = t * 64;
        if (k0 > wmaxrow) continue;   // fully-masked tile: exact no-op skip

        unsigned Ksb = kvb + (unsigned)(t % KVSTG) * (KV_STAGE_H * 2);
        unsigned Vsb = Ksb + (unsigned)(64 * KVP) * 2;

        float s[8][4];
        #pragma unroll
        for (int i = 0; i < 8; ++i)
            #pragma unroll
            for (int j = 0; j < 4; ++j) s[i][j] = 0.f;

        int krow = (lane & 7) + ((lane >> 4) << 3);
        int kcol = ((lane >> 3) & 1) << 3;
        #pragma unroll
        for (int ch = 0; ch < 4; ++ch) {
            unsigned kf[4][4];
            #pragma unroll
            for (int p = 0; p < 4; ++p)
                ldsm4(kf[p], Ksb + (unsigned)((p * 16 + krow) * KVP + ch * 16 + kcol) * 2);
            #pragma unroll
            for (int nt = 0; nt < 8; ++nt)
                mma16816(s[nt], qf[ch],
                         kf[nt >> 1][(nt & 1) * 2 + 0],
                         kf[nt >> 1][(nt & 1) * 2 + 1]);
        }

        if (k0 + 63 > r0g + 8) {
            #pragma unroll
            for (int nt = 0; nt < 8; ++nt) {
                int c0 = k0 + nt * 8 + 2 * tig;
                if (c0     > r0g)     s[nt][0] = -1e30f;
                if (c0 + 1 > r0g)     s[nt][1] = -1e30f;
                if (c0     > r0g + 8) s[nt][2] = -1e30f;
                if (c0 + 1 > r0g + 8) s[nt][3] = -1e30f;
            }
        }

        float mx0 = -1e30f, mx1 = -1e30f;
        #pragma unroll
        for (int nt = 0; nt < 8; ++nt) {
            mx0 = fmaxf(mx0, fmaxf(s[nt][0], s[nt][1]));
            mx1 = fmaxf(mx1, fmaxf(s[nt][2], s[nt][3]));
        }
        mx0 = fmaxf(mx0, __shfl_xor_sync(0xffffffffu, mx0, 1));
        mx0 = fmaxf(mx0, __shfl_xor_sync(0xffffffffu, mx0, 2));
        mx1 = fmaxf(mx1, __shfl_xor_sync(0xffffffffu, mx1, 1));
        mx1 = fmaxf(mx1, __shfl_xor_sync(0xffffffffu, mx1, 2));

        float mn0 = fmaxf(m0, mx0), mn1 = fmaxf(m1, mx1);
        float cr0 = exp2f(m0 - mn0), cr1 = exp2f(m1 - mn1);
        m0 = mn0; m1 = mn1;

        #pragma unroll
        for (int nt = 0; nt < 8; ++nt) {
            o[nt][0] *= cr0; o[nt][1] *= cr0;
            o[nt][2] *= cr1; o[nt][3] *= cr1;
        }
        lacc[0] *= cr0; lacc[1] *= cr0;
        lacc[2] *= cr1; lacc[3] *= cr1;

        int vrow = (lane & 7) + (((lane >> 3) & 1) << 3);
        int vcol = (lane >> 4) << 3;
        #pragma unroll
        for (int c = 0; c < 4; ++c) {
            unsigned pa[4];
            pa[0] = h2exp2_u(f22h2(s[2 * c][0] - mn0, s[2 * c][1] - mn0));
            pa[1] = h2exp2_u(f22h2(s[2 * c][2] - mn1, s[2 * c][3] - mn1));
            pa[2] = h2exp2_u(f22h2(s[2 * c + 1][0] - mn0, s[2 * c + 1][1] - mn0));
            pa[3] = h2exp2_u(f22h2(s[2 * c + 1][2] - mn1, s[2 * c + 1][3] - mn1));

            unsigned vf[4][4];
            #pragma unroll
            for (int p = 0; p < 4; ++p)
                ldsm4t(vf[p], Vsb + (unsigned)((c * 16 + vrow) * KVP + p * 16 + vcol) * 2);

            #pragma unroll
            for (int dt = 0; dt < 8; ++dt)
                mma16816(o[dt], pa,
                         vf[dt >> 1][(dt & 1) * 2 + 0],
                         vf[dt >> 1][(dt & 1) * 2 + 1]);

            mma16816(lacc, pa, w0c, w1c);
        }
    }

    float l0 = __shfl_sync(0xffffffffu, lacc[0], lane & ~3);
    float l1 = __shfl_sync(0xffffffffu, lacc[2], lane & ~3);
    float i0 = 1.f / l0, i1 = 1.f / l1;
    __half* y0 = y + (bT + r0g) * CDIM + h * HDIM;
    __half* y1 = y0 + 8 * CDIM;
    #pragma unroll
    for (int dt = 0; dt < 8; ++dt) {
        __half2 a, bb;
        a.x  = __float2half_rn(o[dt][0] * i0);
        a.y  = __float2half_rn(o[dt][1] * i0);
        bb.x = __float2half_rn(o[dt][2] * i1);
        bb.y = __float2half_rn(o[dt][3] * i1);
        *(__half2*)(y0 + dt * 8 + 2 * tig) = a;
        *(__half2*)(y1 + dt * 8 + 2 * tig) = bb;
    }
}

// ---------------- launch --------------------------------------------------
extern "C" void kernel_launch(void* const* d_in, const int* in_sizes, int n_in,
                              void* d_out, int out_size) {
    const float* x      = (const float*)d_in[0];
    const float* ln1_g  = (const float*)d_in[1];
    const float* ln1_b  = (const float*)d_in[2];
    const float* w_qkv  = (const float*)d_in[3];
    const float* w_o    = (const float*)d_in[4];
    const float* ln2_g  = (const float*)d_in[5];
    const float* ln2_b  = (const float*)d_in[6];
    const float* w_fc   = (const float*)d_in[7];
    const float* b_fc   = (const float*)d_in[8];
    const float* w_proj = (const float*)d_in[9];
    const float* b_proj = (const float*)d_in[10];
    float* out = (float*)d_out;

    __half *lnh, *qkvh, *atth, *hh, *wqkv_h, *wo_h, *wfc_h, *wproj_h;
    float *x1;
    cudaGetSymbolAddress((void**)&lnh,  g_lnh);
    cudaGetSymbolAddress((void**)&qkvh, g_qkvh);
    cudaGetSymbolAddress((void**)&atth, g_atth);
    cudaGetSymbolAddress((void**)&x1,   g_x1);
    cudaGetSymbolAddress((void**)&hh,   g_hh);
    cudaGetSymbolAddress((void**)&wqkv_h,  g_wqkv_h);
    cudaGetSymbolAddress((void**)&wo_h,    g_wo_h);
    cudaGetSymbolAddress((void**)&wfc_h,   g_wfc_h);
    cudaGetSymbolAddress((void**)&wproj_h, g_wproj_h);

    static cudaStream_t s1 = nullptr, s2 = nullptr;
    static cudaEvent_t evF = nullptr, evA = nullptr, evB = nullptr;
    static int smem_set = 0;
    if (!smem_set) {
        cudaFuncSetAttribute(attn_k, cudaFuncAttributeMaxDynamicSharedMemorySize, ATT_SMEM);
        cudaFuncSetAttribute(gemm_k<2>, cudaFuncAttributeMaxDynamicSharedMemorySize, GEMM_SMEM128);
        cudaFuncSetAttribute(gemm_k<4>, cudaFuncAttributeMaxDynamicSharedMemorySize, GEMM_SMEM128);
        cudaFuncSetAttribute(gemm64_k<1>, cudaFuncAttributeMaxDynamicSharedMemorySize, GEMM_SMEM64);
        cudaFuncSetAttribute(gemm64_k<3>, cudaFuncAttributeMaxDynamicSharedMemorySize, GEMM_SMEM64);
        cudaStreamCreateWithFlags(&s1, cudaStreamNonBlocking);
        cudaStreamCreateWithFlags(&s2, cudaStreamNonBlocking);
        cudaEventCreateWithFlags(&evF, cudaEventDisableTiming);
        cudaEventCreateWithFlags(&evA, cudaEventDisableTiming);
        cudaEventCreateWithFlags(&evB, cudaEventDisableTiming);
        smem_set = 1;
    }

    // fork: side streams branch off the main (capture-origin) stream
    cudaEventRecord(evF, 0);
    cudaStreamWaitEvent(s1, evF, 0);
    cudaStreamWaitEvent(s2, evF, 0);

    // s1: qkv weight conversion (needed first)
    round1_k<<<(N4_QKV / 4 + 255) / 256, 256, 0, s1>>>(w_qkv, wqkv_h);
    cudaEventRecord(evA, s1);
    // s2: remaining weight conversions (needed much later)
    round3_k<<<(N4_R3 / 4 + 255) / 256, 256, 0, s2>>>(w_o, w_fc, w_proj,
                                                      wo_h, wfc_h, wproj_h);
    cudaEventRecord(evB, s2);

    // main stream: LN overlaps the conversions
    ln_k<<<ROWS / 8, 256>>>(x, ln1_g, ln1_b, lnh);
    cudaStreamWaitEvent(0, evA, 0);   // join wqkv conversion
    gemm_k<4><<<dim3(3 * CDIM / BN, ROWS / 128), 128, GEMM_SMEM128>>>(lnh, wqkv_h, nullptr, nullptr,
                                                                      qkvh, ROWS, 3 * CDIM, CDIM);
    attn_k<<<dim3(TSEQ / 128, NB * NH), 256, ATT_SMEM>>>(qkvh, atth);
    cudaStreamWaitEvent(0, evB, 0);   // join remaining conversions
    gemm64_k<1><<<dim3(CDIM / BN, ROWS / 64), 128, GEMM_SMEM64>>>(atth, wo_h, nullptr, x,
                                                                  x1, ROWS, CDIM, CDIM);
    ln_k<<<ROWS / 8, 256>>>(x1, ln2_g, ln2_b, lnh);
    gemm_k<2><<<dim3(DFF / BN, ROWS / 128), 128, GEMM_SMEM128>>>(lnh, wfc_h, b_fc, nullptr,
                                                                 hh, ROWS, DFF, CDIM);
    gemm64_k<3><<<dim3(CDIM / BN, ROWS / 64), 128, GEMM_SMEM64>>>(hh, wproj_h, b_proj, x1,
                                                                  out, ROWS, CDIM, DFF);
}